// round 2
// baseline (speedup 1.0000x reference)
#include <cuda_runtime.h>
#include <cuda_bf16.h>
#include <cstdint>

// ---------------------------------------------------------------------------
// BipartiteGConv, CSR-restructured:
//   rhs = input@Wi + bi ; lhs = other@Wo          (one fused GEMM launch)
//   counting-sort edges by rj  ->  (lj_perm, w_perm) grouped per input row
//   row kernel: warp per row, rhs row in regs, stream lhs gathers, no atomics
//   out = acc@(Wf@WoutA) + cnt*(bf@WoutA) + input@WoutB + bout
// ---------------------------------------------------------------------------

#define N_IN_MAX  100000
#define N_OT_MAX  50000
#define E_MAX     1050000

__device__ float g_rhs[N_IN_MAX * 64];
__device__ float g_lhs[N_OT_MAX * 64];
__device__ float g_acc[N_IN_MAX * 64];
__device__ int   g_cnt[N_IN_MAX];
__device__ int   g_row_start[N_IN_MAX + 1];
__device__ int   g_cursor[N_IN_MAX];
__device__ int   g_lj_perm[E_MAX];
__device__ float g_w_perm[E_MAX];
__device__ float g_Wcomb[64 * 64];
__device__ float g_bfw[64];

// ---------------- zero cnt ----------------
__global__ void zero_cnt_kernel(int* __restrict__ cnt, int n) {
    int i = blockIdx.x * blockDim.x + threadIdx.x;
    if (i < n) cnt[i] = 0;
}

// ---------------- histogram of rj ----------------
__global__ void hist_kernel(const int* __restrict__ rj, int* __restrict__ cnt, int E) {
    int e = blockIdx.x * blockDim.x + threadIdx.x;
    if (e < E) atomicAdd(cnt + __ldg(rj + e), 1);
}

// ---------------- single-block exclusive scan over cnt ----------------
__global__ void scan_kernel(const int* __restrict__ cnt,
                            int* __restrict__ row_start,
                            int* __restrict__ cursor, int N) {
    __shared__ int sums[1024];
    const int tid = threadIdx.x;
    const int chunk = (N + 1023) / 1024;
    const int s0 = min(N, tid * chunk);
    const int s1 = min(N, s0 + chunk);

    int sum = 0;
#pragma unroll 4
    for (int i = s0; i < s1; i++) sum += cnt[i];
    sums[tid] = sum;
    __syncthreads();

    // Hillis-Steele inclusive scan -> convert to exclusive
    int v = sum;
#pragma unroll
    for (int d = 1; d < 1024; d <<= 1) {
        int t = (tid >= d) ? sums[tid - d] : 0;
        __syncthreads();
        v += t;
        sums[tid] = v;
        __syncthreads();
    }
    int off = v - sum;  // exclusive prefix for this thread's chunk

    for (int i = s0; i < s1; i++) {
        row_start[i] = off;
        cursor[i] = off;
        off += cnt[i];
    }
    if (s1 == N && s0 <= N) row_start[N] = off;
}

// ---------------- scatter (lj, w) into row-grouped order ----------------
__global__ void scatter_kernel(const int* __restrict__ rj,
                               const int* __restrict__ lj,
                               const float* __restrict__ w,
                               int* __restrict__ cursor,
                               int* __restrict__ lj_perm,
                               float* __restrict__ w_perm, int E) {
    int e = blockIdx.x * blockDim.x + threadIdx.x;
    if (e >= E) return;
    int r = __ldg(rj + e);
    int p = atomicAdd(cursor + r, 1);
    lj_perm[p] = __ldg(lj + e);
    w_perm[p] = __ldg(w + e);
}

// ---------------- fused input GEMMs: rhs = input@Wi+bi, lhs = other@Wo -------
// 64x64 tile per block, 256 threads, 4x4 register tile.
__global__ void gemm_both_kernel(const float* __restrict__ input,
                                 const float* __restrict__ Wi,
                                 const float* __restrict__ bi,
                                 const float* __restrict__ other,
                                 const float* __restrict__ Wo,
                                 float* __restrict__ rhs,
                                 float* __restrict__ lhs,
                                 int M_in, int M_ot, int blocks_in) {
    __shared__ float As[64][65];
    __shared__ float Ws[64][65];

    const bool is_in = (int)blockIdx.x < blocks_in;
    const float* A = is_in ? input : other;
    const float* W = is_in ? Wi : Wo;
    const float* bias = is_in ? bi : nullptr;
    float* C = is_in ? rhs : lhs;
    const int M = is_in ? M_in : M_ot;
    const int block_row = (is_in ? blockIdx.x : (blockIdx.x - blocks_in)) * 64;
    const int tid = threadIdx.x;

    for (int i = tid; i < 64 * 64; i += 256) {
        int r = i >> 6, c = i & 63;
        int grow = block_row + r;
        As[c][r] = (grow < M) ? A[(size_t)grow * 64 + c] : 0.0f;
        Ws[r][c] = W[i];
    }
    __syncthreads();

    const int tx = tid & 15;
    const int ty = tid >> 4;
    float acc[4][4] = {};
#pragma unroll 8
    for (int k = 0; k < 64; k++) {
        float a0 = As[k][ty * 4 + 0], a1 = As[k][ty * 4 + 1];
        float a2 = As[k][ty * 4 + 2], a3 = As[k][ty * 4 + 3];
        float b0 = Ws[k][tx * 4 + 0], b1 = Ws[k][tx * 4 + 1];
        float b2 = Ws[k][tx * 4 + 2], b3 = Ws[k][tx * 4 + 3];
        acc[0][0] = fmaf(a0, b0, acc[0][0]); acc[0][1] = fmaf(a0, b1, acc[0][1]);
        acc[0][2] = fmaf(a0, b2, acc[0][2]); acc[0][3] = fmaf(a0, b3, acc[0][3]);
        acc[1][0] = fmaf(a1, b0, acc[1][0]); acc[1][1] = fmaf(a1, b1, acc[1][1]);
        acc[1][2] = fmaf(a1, b2, acc[1][2]); acc[1][3] = fmaf(a1, b3, acc[1][3]);
        acc[2][0] = fmaf(a2, b0, acc[2][0]); acc[2][1] = fmaf(a2, b1, acc[2][1]);
        acc[2][2] = fmaf(a2, b2, acc[2][2]); acc[2][3] = fmaf(a2, b3, acc[2][3]);
        acc[3][0] = fmaf(a3, b0, acc[3][0]); acc[3][1] = fmaf(a3, b1, acc[3][1]);
        acc[3][2] = fmaf(a3, b2, acc[3][2]); acc[3][3] = fmaf(a3, b3, acc[3][3]);
    }

    float bv[4] = {0.f, 0.f, 0.f, 0.f};
    if (bias) {
#pragma unroll
        for (int j = 0; j < 4; j++) bv[j] = bias[tx * 4 + j];
    }
#pragma unroll
    for (int i = 0; i < 4; i++) {
        int row = block_row + ty * 4 + i;
        if (row < M) {
            float4 v = make_float4(acc[i][0] + bv[0], acc[i][1] + bv[1],
                                   acc[i][2] + bv[2], acc[i][3] + bv[3]);
            *reinterpret_cast<float4*>(&C[(size_t)row * 64 + tx * 4]) = v;
        }
    }
}

// ---------------- row accumulate: warp per row, no atomics --------------------
__global__ void row_kernel(const float* __restrict__ rhs,
                           const float* __restrict__ lhs,
                           const int* __restrict__ row_start,
                           const int* __restrict__ lj_perm,
                           const float* __restrict__ w_perm,
                           const float* __restrict__ We,
                           float* __restrict__ acc, int N) {
    const int row = blockIdx.x * (blockDim.x >> 5) + (threadIdx.x >> 5);
    if (row >= N) return;
    const int lane = threadIdx.x & 31;

    const float2* rhs2 = reinterpret_cast<const float2*>(rhs);
    const float2* lhs2 = reinterpret_cast<const float2*>(lhs);
    const float2* We2  = reinterpret_cast<const float2*>(We);

    const float2 r  = __ldg(rhs2 + (size_t)row * 32 + lane);
    const float2 we = __ldg(We2 + lane);

    const int s = __ldg(row_start + row);
    const int t = __ldg(row_start + row + 1);

    float2 a = make_float2(0.0f, 0.0f);
    for (int base = s; base < t; base += 32) {
        const int n = min(32, t - base);
        int ljv = 0;
        float wv = 0.0f;
        if (lane < n) {
            ljv = __ldg(lj_perm + base + lane);
            wv  = __ldg(w_perm + base + lane);
        }
#pragma unroll 4
        for (int j = 0; j < n; j++) {
            int   l = __shfl_sync(0xffffffffu, ljv, j);
            float w = __shfl_sync(0xffffffffu, wv, j);
            float2 b = __ldg(lhs2 + (size_t)l * 32 + lane);
            float mx = fmaf(w, we.x, r.x + b.x);
            float my = fmaf(w, we.y, r.y + b.y);
            mx = fmaxf(mx, 0.f) + 0.01f * fminf(mx, 0.f);
            my = fmaxf(my, 0.f) + 0.01f * fminf(my, 0.f);
            a.x += mx;
            a.y += my;
        }
    }
    reinterpret_cast<float2*>(acc)[(size_t)row * 32 + lane] = a;
}

// ---------------- precompute Wcomb = Wf@Wout[0:64,:], bfw = bf@Wout[0:64,:] ---
__global__ void precompute_kernel(const float* __restrict__ Wf,
                                  const float* __restrict__ bf,
                                  const float* __restrict__ Wout,
                                  float* __restrict__ Wcomb,
                                  float* __restrict__ bfw) {
    int tid = blockIdx.x * blockDim.x + threadIdx.x;
    if (tid < 64 * 64) {
        int k = tid >> 6, d = tid & 63;
        float s0 = 0.f, s1 = 0.f, s2 = 0.f, s3 = 0.f;
#pragma unroll
        for (int j = 0; j < 64; j += 4) {
            s0 = fmaf(__ldg(Wf + k * 64 + j + 0), __ldg(Wout + (j + 0) * 64 + d), s0);
            s1 = fmaf(__ldg(Wf + k * 64 + j + 1), __ldg(Wout + (j + 1) * 64 + d), s1);
            s2 = fmaf(__ldg(Wf + k * 64 + j + 2), __ldg(Wout + (j + 2) * 64 + d), s2);
            s3 = fmaf(__ldg(Wf + k * 64 + j + 3), __ldg(Wout + (j + 3) * 64 + d), s3);
        }
        Wcomb[tid] = (s0 + s1) + (s2 + s3);
    }
    if (tid < 64) {
        float s0 = 0.f, s1 = 0.f;
#pragma unroll
        for (int j = 0; j < 64; j += 2) {
            s0 = fmaf(__ldg(bf + j + 0), __ldg(Wout + (j + 0) * 64 + tid), s0);
            s1 = fmaf(__ldg(bf + j + 1), __ldg(Wout + (j + 1) * 64 + tid), s1);
        }
        bfw[tid] = s0 + s1;
    }
}

// ---------------- fused epilogue: K=128 GEMM + cnt term + biases --------------
__global__ void final_kernel(const float* __restrict__ accm,
                             const float* __restrict__ input,
                             const int* __restrict__ cnt,
                             const float* __restrict__ Wcomb,
                             const float* __restrict__ WoutB,
                             const float* __restrict__ bfw,
                             const float* __restrict__ bout,
                             float* __restrict__ out, int M) {
    __shared__ float As[64][65];
    __shared__ float Ws[64][65];
    const int block_row = blockIdx.x * 64;
    const int tid = threadIdx.x;
    const int tx = tid & 15;
    const int ty = tid >> 4;

    float acc[4][4] = {};

#pragma unroll
    for (int p = 0; p < 2; p++) {
        const float* Ap = (p == 0) ? accm : input;
        const float* Wp = (p == 0) ? Wcomb : WoutB;
        for (int i = tid; i < 64 * 64; i += 256) {
            int r = i >> 6, c = i & 63;
            int grow = block_row + r;
            As[c][r] = (grow < M) ? Ap[(size_t)grow * 64 + c] : 0.0f;
            Ws[r][c] = Wp[i];
        }
        __syncthreads();
#pragma unroll 8
        for (int k = 0; k < 64; k++) {
            float a0 = As[k][ty * 4 + 0], a1 = As[k][ty * 4 + 1];
            float a2 = As[k][ty * 4 + 2], a3 = As[k][ty * 4 + 3];
            float b0 = Ws[k][tx * 4 + 0], b1 = Ws[k][tx * 4 + 1];
            float b2 = Ws[k][tx * 4 + 2], b3 = Ws[k][tx * 4 + 3];
            acc[0][0] = fmaf(a0, b0, acc[0][0]); acc[0][1] = fmaf(a0, b1, acc[0][1]);
            acc[0][2] = fmaf(a0, b2, acc[0][2]); acc[0][3] = fmaf(a0, b3, acc[0][3]);
            acc[1][0] = fmaf(a1, b0, acc[1][0]); acc[1][1] = fmaf(a1, b1, acc[1][1]);
            acc[1][2] = fmaf(a1, b2, acc[1][2]); acc[1][3] = fmaf(a1, b3, acc[1][3]);
            acc[2][0] = fmaf(a2, b0, acc[2][0]); acc[2][1] = fmaf(a2, b1, acc[2][1]);
            acc[2][2] = fmaf(a2, b2, acc[2][2]); acc[2][3] = fmaf(a2, b3, acc[2][3]);
            acc[3][0] = fmaf(a3, b0, acc[3][0]); acc[3][1] = fmaf(a3, b1, acc[3][1]);
            acc[3][2] = fmaf(a3, b2, acc[3][2]); acc[3][3] = fmaf(a3, b3, acc[3][3]);
        }
        __syncthreads();
    }

    float bfv[4], bov[4];
#pragma unroll
    for (int j = 0; j < 4; j++) {
        bfv[j] = bfw[tx * 4 + j];
        bov[j] = bout[tx * 4 + j];
    }
#pragma unroll
    for (int i = 0; i < 4; i++) {
        int row = block_row + ty * 4 + i;
        if (row < M) {
            float c = (float)cnt[row];
            float4 v = make_float4(acc[i][0] + c * bfv[0] + bov[0],
                                   acc[i][1] + c * bfv[1] + bov[1],
                                   acc[i][2] + c * bfv[2] + bov[2],
                                   acc[i][3] + c * bfv[3] + bov[3]);
            *reinterpret_cast<float4*>(&out[(size_t)row * 64 + tx * 4]) = v;
        }
    }
}

// ---------------------------------------------------------------------------
extern "C" void kernel_launch(void* const* d_in, const int* in_sizes, int n_in,
                              void* d_out, int out_size) {
    const float* input   = (const float*)d_in[0];
    const float* other   = (const float*)d_in[1];
    const int*   rj      = (const int*)d_in[2];
    const int*   lj      = (const int*)d_in[3];
    const float* weights = (const float*)d_in[4];
    const float* Wi      = (const float*)d_in[5];
    const float* bi      = (const float*)d_in[6];
    const float* Wo      = (const float*)d_in[7];
    const float* We      = (const float*)d_in[8];
    const float* Wf      = (const float*)d_in[9];
    const float* bf      = (const float*)d_in[10];
    const float* Wout    = (const float*)d_in[11];
    const float* bout    = (const float*)d_in[12];
    float* out = (float*)d_out;

    const int N_IN = in_sizes[0] / 64;
    const int N_OT = in_sizes[1] / 64;
    const int E    = in_sizes[2];

    float *rhs, *lhs, *acc, *w_perm, *Wcomb, *bfw;
    int *cnt, *row_start, *cursor, *lj_perm;
    cudaGetSymbolAddress((void**)&rhs,       g_rhs);
    cudaGetSymbolAddress((void**)&lhs,       g_lhs);
    cudaGetSymbolAddress((void**)&acc,       g_acc);
    cudaGetSymbolAddress((void**)&cnt,       g_cnt);
    cudaGetSymbolAddress((void**)&row_start, g_row_start);
    cudaGetSymbolAddress((void**)&cursor,    g_cursor);
    cudaGetSymbolAddress((void**)&lj_perm,   g_lj_perm);
    cudaGetSymbolAddress((void**)&w_perm,    g_w_perm);
    cudaGetSymbolAddress((void**)&Wcomb,     g_Wcomb);
    cudaGetSymbolAddress((void**)&bfw,       g_bfw);

    // 1. counting sort of edges by rj
    zero_cnt_kernel<<<(N_IN + 255) / 256, 256>>>(cnt, N_IN);
    hist_kernel<<<(E + 255) / 256, 256>>>(rj, cnt, E);
    scan_kernel<<<1, 1024>>>(cnt, row_start, cursor, N_IN);
    scatter_kernel<<<(E + 255) / 256, 256>>>(rj, lj, weights, cursor,
                                             lj_perm, w_perm, E);

    // 2. fused input-side GEMMs (rhs and lhs in one launch)
    {
        int blocks_in = (N_IN + 63) / 64;
        int blocks_ot = (N_OT + 63) / 64;
        gemm_both_kernel<<<blocks_in + blocks_ot, 256>>>(
            input, Wi, bi, other, Wo, rhs, lhs, N_IN, N_OT, blocks_in);
    }

    // 3. per-row edge accumulation (warp per row, atomic-free)
    row_kernel<<<(N_IN + 7) / 8, 256>>>(rhs, lhs, row_start, lj_perm, w_perm,
                                        We, acc, N_IN);

    // 4. folded epilogue weights
    precompute_kernel<<<16, 256>>>(Wf, bf, Wout, Wcomb, bfw);

    // 5. fused epilogue GEMM (K=128) + cnt*bfw + bout
    final_kernel<<<(N_IN + 63) / 64, 256>>>(acc, input, cnt, Wcomb,
                                            Wout + 64 * 64, bfw, bout, out, N_IN);
}

// round 3
// speedup vs baseline: 1.7953x; 1.7953x over previous
#include <cuda_runtime.h>
#include <cuda_bf16.h>
#include <cstdint>

// ---------------------------------------------------------------------------
// BipartiteGConv, CSR-restructured (fixed multi-block scan, broadcast row kernel)
//   rhs = input@Wi + bi ; lhs = other@Wo          (one fused GEMM launch)
//   counting-sort edges by rj  ->  packed (lj,w) float2 per edge, row-grouped
//   row kernel: warp per row, rhs row in regs, lhs gathers MLP-unrolled, no shfl
//   out = acc@(Wf@WoutA) + cnt*(bf@WoutA) + input@WoutB + bout
// ---------------------------------------------------------------------------

#define N_IN_MAX  100000
#define N_OT_MAX  50000
#define E_MAX     1050000
#define SCAN_B    1024

__device__ float  g_rhs[N_IN_MAX * 64];
__device__ float  g_lhs[N_OT_MAX * 64];
__device__ float  g_acc[N_IN_MAX * 64];
__device__ int    g_cnt[N_IN_MAX];
__device__ int    g_row_start[N_IN_MAX + 1];
__device__ int    g_cursor[N_IN_MAX];
__device__ int    g_bsum[1024];
__device__ float2 g_edges[E_MAX];           // packed (lj as int bits, w)
__device__ float  g_Wcomb[64 * 64];
__device__ float  g_bfw[64];

// ---------------- zero cnt ----------------
__global__ void zero_cnt_kernel(int* __restrict__ cnt, int n) {
    int i = blockIdx.x * blockDim.x + threadIdx.x;
    if (i < n) cnt[i] = 0;
}

// ---------------- histogram of rj ----------------
__global__ void hist_kernel(const int* __restrict__ rj, int* __restrict__ cnt, int E) {
    int e = blockIdx.x * blockDim.x + threadIdx.x;
    if (e < E) atomicAdd(cnt + __ldg(rj + e), 1);
}

// ---------------- scan1: per-block exclusive scan + block sums ----------------
__global__ void scan1_kernel(const int* __restrict__ cnt,
                             int* __restrict__ excl,
                             int* __restrict__ bsum, int N) {
    __shared__ int s[SCAN_B];
    const int tid = threadIdx.x;
    const int i = blockIdx.x * SCAN_B + tid;
    int v = (i < N) ? cnt[i] : 0;
    s[tid] = v;
    __syncthreads();
    int x = v;
#pragma unroll
    for (int d = 1; d < SCAN_B; d <<= 1) {
        int t = (tid >= d) ? s[tid - d] : 0;
        __syncthreads();
        x += t;
        s[tid] = x;
        __syncthreads();
    }
    if (i < N) excl[i] = x - v;
    if (tid == SCAN_B - 1) bsum[blockIdx.x] = x;
}

// ---------------- scan2: single small block scans block sums ------------------
__global__ void scan2_kernel(int* __restrict__ bsum, int NB) {
    __shared__ int s[1024];
    const int tid = threadIdx.x;
    int v = (tid < NB) ? bsum[tid] : 0;
    s[tid] = v;
    __syncthreads();
    int x = v;
#pragma unroll
    for (int d = 1; d < 1024; d <<= 1) {
        int t = (tid >= d) ? s[tid - d] : 0;
        __syncthreads();
        x += t;
        s[tid] = x;
        __syncthreads();
    }
    if (tid < NB) bsum[tid] = x - v;  // exclusive block offsets
}

// ---------------- scan3: add offsets, init cursor, cap row_start --------------
__global__ void scan3_kernel(int* __restrict__ row_start,
                             const int* __restrict__ bsum,
                             int* __restrict__ cursor, int N, int E) {
    const int i = blockIdx.x * SCAN_B + threadIdx.x;
    if (i < N) {
        int v = row_start[i] + bsum[blockIdx.x];
        row_start[i] = v;
        cursor[i] = v;
    }
    if (i == 0) row_start[N] = E;
}

// ---------------- scatter packed edges into row-grouped order -----------------
__global__ void scatter_kernel(const int* __restrict__ rj,
                               const int* __restrict__ lj,
                               const float* __restrict__ w,
                               int* __restrict__ cursor,
                               float2* __restrict__ edges, int E) {
    int e = blockIdx.x * blockDim.x + threadIdx.x;
    if (e >= E) return;
    int r = __ldg(rj + e);
    int p = atomicAdd(cursor + r, 1);
    edges[p] = make_float2(__int_as_float(__ldg(lj + e)), __ldg(w + e));
}

// ---------------- fused input GEMMs: rhs = input@Wi+bi, lhs = other@Wo --------
__global__ void gemm_both_kernel(const float* __restrict__ input,
                                 const float* __restrict__ Wi,
                                 const float* __restrict__ bi,
                                 const float* __restrict__ other,
                                 const float* __restrict__ Wo,
                                 float* __restrict__ rhs,
                                 float* __restrict__ lhs,
                                 int M_in, int M_ot, int blocks_in) {
    __shared__ float As[64][65];
    __shared__ float Ws[64][65];

    const bool is_in = (int)blockIdx.x < blocks_in;
    const float* A = is_in ? input : other;
    const float* W = is_in ? Wi : Wo;
    const float* bias = is_in ? bi : nullptr;
    float* C = is_in ? rhs : lhs;
    const int M = is_in ? M_in : M_ot;
    const int block_row = (is_in ? blockIdx.x : (blockIdx.x - blocks_in)) * 64;
    const int tid = threadIdx.x;

    for (int i = tid; i < 64 * 64; i += 256) {
        int r = i >> 6, c = i & 63;
        int grow = block_row + r;
        As[c][r] = (grow < M) ? A[(size_t)grow * 64 + c] : 0.0f;
        Ws[r][c] = W[i];
    }
    __syncthreads();

    const int tx = tid & 15;
    const int ty = tid >> 4;
    float acc[4][4] = {};
#pragma unroll 8
    for (int k = 0; k < 64; k++) {
        float a0 = As[k][ty * 4 + 0], a1 = As[k][ty * 4 + 1];
        float a2 = As[k][ty * 4 + 2], a3 = As[k][ty * 4 + 3];
        float b0 = Ws[k][tx * 4 + 0], b1 = Ws[k][tx * 4 + 1];
        float b2 = Ws[k][tx * 4 + 2], b3 = Ws[k][tx * 4 + 3];
        acc[0][0] = fmaf(a0, b0, acc[0][0]); acc[0][1] = fmaf(a0, b1, acc[0][1]);
        acc[0][2] = fmaf(a0, b2, acc[0][2]); acc[0][3] = fmaf(a0, b3, acc[0][3]);
        acc[1][0] = fmaf(a1, b0, acc[1][0]); acc[1][1] = fmaf(a1, b1, acc[1][1]);
        acc[1][2] = fmaf(a1, b2, acc[1][2]); acc[1][3] = fmaf(a1, b3, acc[1][3]);
        acc[2][0] = fmaf(a2, b0, acc[2][0]); acc[2][1] = fmaf(a2, b1, acc[2][1]);
        acc[2][2] = fmaf(a2, b2, acc[2][2]); acc[2][3] = fmaf(a2, b3, acc[2][3]);
        acc[3][0] = fmaf(a3, b0, acc[3][0]); acc[3][1] = fmaf(a3, b1, acc[3][1]);
        acc[3][2] = fmaf(a3, b2, acc[3][2]); acc[3][3] = fmaf(a3, b3, acc[3][3]);
    }

    float bv[4] = {0.f, 0.f, 0.f, 0.f};
    if (bias) {
#pragma unroll
        for (int j = 0; j < 4; j++) bv[j] = bias[tx * 4 + j];
    }
#pragma unroll
    for (int i = 0; i < 4; i++) {
        int row = block_row + ty * 4 + i;
        if (row < M) {
            float4 v = make_float4(acc[i][0] + bv[0], acc[i][1] + bv[1],
                                   acc[i][2] + bv[2], acc[i][3] + bv[3]);
            *reinterpret_cast<float4*>(&C[(size_t)row * 64 + tx * 4]) = v;
        }
    }
}

// ---------------- row accumulate: warp per row, broadcast edge reads ----------
__device__ __forceinline__ float lrelu(float x) {
    return fmaxf(x, 0.f) + 0.01f * fminf(x, 0.f);
}

__global__ void row_kernel(const float* __restrict__ rhs,
                           const float* __restrict__ lhs,
                           const int* __restrict__ row_start,
                           const float2* __restrict__ edges,
                           const float* __restrict__ We,
                           float* __restrict__ acc, int N) {
    const int row = blockIdx.x * (blockDim.x >> 5) + (threadIdx.x >> 5);
    if (row >= N) return;
    const int lane = threadIdx.x & 31;

    const float2* rhs2 = reinterpret_cast<const float2*>(rhs);
    const float2* lhs2 = reinterpret_cast<const float2*>(lhs);
    const float2* We2  = reinterpret_cast<const float2*>(We);

    const float2 r  = __ldg(rhs2 + (size_t)row * 32 + lane);
    const float2 we = __ldg(We2 + lane);

    const int s = __ldg(row_start + row);
    const int t = __ldg(row_start + row + 1);

    float ax = 0.f, ay = 0.f, bx = 0.f, by = 0.f;
    int j = s;
#pragma unroll 2
    for (; j + 2 <= t; j += 2) {
        // all lanes read same edge word -> warp-broadcast, L1-resident
        float2 e0 = __ldg(edges + j);
        float2 e1 = __ldg(edges + j + 1);
        int l0 = __float_as_int(e0.x);
        int l1 = __float_as_int(e1.x);
        float2 v0 = __ldg(lhs2 + (size_t)l0 * 32 + lane);
        float2 v1 = __ldg(lhs2 + (size_t)l1 * 32 + lane);
        ax += lrelu(fmaf(e0.y, we.x, r.x + v0.x));
        ay += lrelu(fmaf(e0.y, we.y, r.y + v0.y));
        bx += lrelu(fmaf(e1.y, we.x, r.x + v1.x));
        by += lrelu(fmaf(e1.y, we.y, r.y + v1.y));
    }
    if (j < t) {
        float2 e0 = __ldg(edges + j);
        int l0 = __float_as_int(e0.x);
        float2 v0 = __ldg(lhs2 + (size_t)l0 * 32 + lane);
        ax += lrelu(fmaf(e0.y, we.x, r.x + v0.x));
        ay += lrelu(fmaf(e0.y, we.y, r.y + v0.y));
    }
    reinterpret_cast<float2*>(acc)[(size_t)row * 32 + lane] =
        make_float2(ax + bx, ay + by);
}

// ---------------- precompute Wcomb = Wf@Wout[0:64,:], bfw = bf@Wout[0:64,:] ---
__global__ void precompute_kernel(const float* __restrict__ Wf,
                                  const float* __restrict__ bf,
                                  const float* __restrict__ Wout,
                                  float* __restrict__ Wcomb,
                                  float* __restrict__ bfw) {
    int tid = blockIdx.x * blockDim.x + threadIdx.x;
    if (tid < 64 * 64) {
        int k = tid >> 6, d = tid & 63;
        float s0 = 0.f, s1 = 0.f, s2 = 0.f, s3 = 0.f;
#pragma unroll
        for (int j = 0; j < 64; j += 4) {
            s0 = fmaf(__ldg(Wf + k * 64 + j + 0), __ldg(Wout + (j + 0) * 64 + d), s0);
            s1 = fmaf(__ldg(Wf + k * 64 + j + 1), __ldg(Wout + (j + 1) * 64 + d), s1);
            s2 = fmaf(__ldg(Wf + k * 64 + j + 2), __ldg(Wout + (j + 2) * 64 + d), s2);
            s3 = fmaf(__ldg(Wf + k * 64 + j + 3), __ldg(Wout + (j + 3) * 64 + d), s3);
        }
        Wcomb[tid] = (s0 + s1) + (s2 + s3);
    }
    if (tid < 64) {
        float s0 = 0.f, s1 = 0.f;
#pragma unroll
        for (int j = 0; j < 64; j += 2) {
            s0 = fmaf(__ldg(bf + j + 0), __ldg(Wout + (j + 0) * 64 + tid), s0);
            s1 = fmaf(__ldg(bf + j + 1), __ldg(Wout + (j + 1) * 64 + tid), s1);
        }
        bfw[tid] = s0 + s1;
    }
}

// ---------------- fused epilogue: K=128 GEMM + cnt term + biases --------------
__global__ void final_kernel(const float* __restrict__ accm,
                             const float* __restrict__ input,
                             const int* __restrict__ row_start,
                             const float* __restrict__ Wcomb,
                             const float* __restrict__ WoutB,
                             const float* __restrict__ bfw,
                             const float* __restrict__ bout,
                             float* __restrict__ out, int M) {
    __shared__ float As[64][65];
    __shared__ float Ws[64][65];
    const int block_row = blockIdx.x * 64;
    const int tid = threadIdx.x;
    const int tx = tid & 15;
    const int ty = tid >> 4;

    float acc[4][4] = {};

#pragma unroll
    for (int p = 0; p < 2; p++) {
        const float* Ap = (p == 0) ? accm : input;
        const float* Wp = (p == 0) ? Wcomb : WoutB;
        for (int i = tid; i < 64 * 64; i += 256) {
            int r = i >> 6, c = i & 63;
            int grow = block_row + r;
            As[c][r] = (grow < M) ? Ap[(size_t)grow * 64 + c] : 0.0f;
            Ws[r][c] = Wp[i];
        }
        __syncthreads();
#pragma unroll 8
        for (int k = 0; k < 64; k++) {
            float a0 = As[k][ty * 4 + 0], a1 = As[k][ty * 4 + 1];
            float a2 = As[k][ty * 4 + 2], a3 = As[k][ty * 4 + 3];
            float b0 = Ws[k][tx * 4 + 0], b1 = Ws[k][tx * 4 + 1];
            float b2 = Ws[k][tx * 4 + 2], b3 = Ws[k][tx * 4 + 3];
            acc[0][0] = fmaf(a0, b0, acc[0][0]); acc[0][1] = fmaf(a0, b1, acc[0][1]);
            acc[0][2] = fmaf(a0, b2, acc[0][2]); acc[0][3] = fmaf(a0, b3, acc[0][3]);
            acc[1][0] = fmaf(a1, b0, acc[1][0]); acc[1][1] = fmaf(a1, b1, acc[1][1]);
            acc[1][2] = fmaf(a1, b2, acc[1][2]); acc[1][3] = fmaf(a1, b3, acc[1][3]);
            acc[2][0] = fmaf(a2, b0, acc[2][0]); acc[2][1] = fmaf(a2, b1, acc[2][1]);
            acc[2][2] = fmaf(a2, b2, acc[2][2]); acc[2][3] = fmaf(a2, b3, acc[2][3]);
            acc[3][0] = fmaf(a3, b0, acc[3][0]); acc[3][1] = fmaf(a3, b1, acc[3][1]);
            acc[3][2] = fmaf(a3, b2, acc[3][2]); acc[3][3] = fmaf(a3, b3, acc[3][3]);
        }
        __syncthreads();
    }

    float bfv[4], bov[4];
#pragma unroll
    for (int j = 0; j < 4; j++) {
        bfv[j] = bfw[tx * 4 + j];
        bov[j] = bout[tx * 4 + j];
    }
#pragma unroll
    for (int i = 0; i < 4; i++) {
        int row = block_row + ty * 4 + i;
        if (row < M) {
            float c = (float)(__ldg(row_start + row + 1) - __ldg(row_start + row));
            float4 v = make_float4(acc[i][0] + c * bfv[0] + bov[0],
                                   acc[i][1] + c * bfv[1] + bov[1],
                                   acc[i][2] + c * bfv[2] + bov[2],
                                   acc[i][3] + c * bfv[3] + bov[3]);
            *reinterpret_cast<float4*>(&out[(size_t)row * 64 + tx * 4]) = v;
        }
    }
}

// ---------------------------------------------------------------------------
extern "C" void kernel_launch(void* const* d_in, const int* in_sizes, int n_in,
                              void* d_out, int out_size) {
    const float* input   = (const float*)d_in[0];
    const float* other   = (const float*)d_in[1];
    const int*   rj      = (const int*)d_in[2];
    const int*   lj      = (const int*)d_in[3];
    const float* weights = (const float*)d_in[4];
    const float* Wi      = (const float*)d_in[5];
    const float* bi      = (const float*)d_in[6];
    const float* Wo      = (const float*)d_in[7];
    const float* We      = (const float*)d_in[8];
    const float* Wf      = (const float*)d_in[9];
    const float* bf      = (const float*)d_in[10];
    const float* Wout    = (const float*)d_in[11];
    const float* bout    = (const float*)d_in[12];
    float* out = (float*)d_out;

    const int N_IN = in_sizes[0] / 64;
    const int N_OT = in_sizes[1] / 64;
    const int E    = in_sizes[2];

    float *rhs, *lhs, *acc, *Wcomb, *bfw;
    float2* edges;
    int *cnt, *row_start, *cursor, *bsum;
    cudaGetSymbolAddress((void**)&rhs,       g_rhs);
    cudaGetSymbolAddress((void**)&lhs,       g_lhs);
    cudaGetSymbolAddress((void**)&acc,       g_acc);
    cudaGetSymbolAddress((void**)&cnt,       g_cnt);
    cudaGetSymbolAddress((void**)&row_start, g_row_start);
    cudaGetSymbolAddress((void**)&cursor,    g_cursor);
    cudaGetSymbolAddress((void**)&bsum,      g_bsum);
    cudaGetSymbolAddress((void**)&edges,     g_edges);
    cudaGetSymbolAddress((void**)&Wcomb,     g_Wcomb);
    cudaGetSymbolAddress((void**)&bfw,       g_bfw);

    const int NB = (N_IN + SCAN_B - 1) / SCAN_B;

    // 1. counting sort of edges by rj (multi-block scan)
    zero_cnt_kernel<<<(N_IN + 255) / 256, 256>>>(cnt, N_IN);
    hist_kernel<<<(E + 255) / 256, 256>>>(rj, cnt, E);
    scan1_kernel<<<NB, SCAN_B>>>(cnt, row_start, bsum, N_IN);
    scan2_kernel<<<1, 1024>>>(bsum, NB);
    scan3_kernel<<<NB, SCAN_B>>>(row_start, bsum, cursor, N_IN, E);
    scatter_kernel<<<(E + 255) / 256, 256>>>(rj, lj, weights, cursor, edges, E);

    // 2. fused input-side GEMMs
    {
        int blocks_in = (N_IN + 63) / 64;
        int blocks_ot = (N_OT + 63) / 64;
        gemm_both_kernel<<<blocks_in + blocks_ot, 256>>>(
            input, Wi, bi, other, Wo, rhs, lhs, N_IN, N_OT, blocks_in);
    }

    // 3. per-row edge accumulation (warp per row, atomic-free, MLP-unrolled)
    row_kernel<<<(N_IN + 7) / 8, 256>>>(rhs, lhs, row_start, edges, We, acc, N_IN);

    // 4. folded epilogue weights
    precompute_kernel<<<16, 256>>>(Wf, bf, Wout, Wcomb, bfw);

    // 5. fused epilogue GEMM (K=128) + cnt*bfw + bout
    final_kernel<<<(N_IN + 63) / 64, 256>>>(acc, input, row_start, Wcomb,
                                            Wout + 64 * 64, bfw, bout, out, N_IN);
}

// round 4
// speedup vs baseline: 2.3683x; 1.3192x over previous
#include <cuda_runtime.h>
#include <cuda_bf16.h>
#include <cstdint>

// ---------------------------------------------------------------------------
// BipartiteGConv, CSR + tf32 tensor-core GEMMs (3xTF32 split for fp32 accuracy)
//   rhs = input@Wi + bi ; lhs = other@Wo          (tf32 mma, one fused launch)
//   counting-sort edges by rj  ->  packed (lj,w) float2 per edge, row-grouped
//   row kernel: warp per row, rhs row in regs, lhs gathers, no atomics
//   out = acc@(Wf@WoutA) + cnt*(bf@WoutA) + input@WoutB + bout  (tf32 mma, K=128)
// ---------------------------------------------------------------------------

#define N_IN_MAX  100000
#define N_OT_MAX  50000
#define E_MAX     1050000
#define SCAN_B    1024

__device__ float  g_rhs[N_IN_MAX * 64];
__device__ float  g_lhs[N_OT_MAX * 64];
__device__ float  g_acc[N_IN_MAX * 64];
__device__ int    g_cnt[N_IN_MAX];
__device__ int    g_row_start[N_IN_MAX + 1];
__device__ int    g_cursor[N_IN_MAX];
__device__ int    g_bsum[1024];
__device__ float2 g_edges[E_MAX];
__device__ float  g_Wcomb[64 * 64];
__device__ float  g_bfw[64];

// ======================= sort pipeline (unchanged from R3) ==================
__global__ void zero_cnt_kernel(int* __restrict__ cnt, int n) {
    int i = blockIdx.x * blockDim.x + threadIdx.x;
    if (i < n) cnt[i] = 0;
}

__global__ void hist_kernel(const int* __restrict__ rj, int* __restrict__ cnt, int E) {
    int e = blockIdx.x * blockDim.x + threadIdx.x;
    if (e < E) atomicAdd(cnt + __ldg(rj + e), 1);
}

__global__ void scan1_kernel(const int* __restrict__ cnt,
                             int* __restrict__ excl,
                             int* __restrict__ bsum, int N) {
    __shared__ int s[SCAN_B];
    const int tid = threadIdx.x;
    const int i = blockIdx.x * SCAN_B + tid;
    int v = (i < N) ? cnt[i] : 0;
    s[tid] = v;
    __syncthreads();
    int x = v;
#pragma unroll
    for (int d = 1; d < SCAN_B; d <<= 1) {
        int t = (tid >= d) ? s[tid - d] : 0;
        __syncthreads();
        x += t;
        s[tid] = x;
        __syncthreads();
    }
    if (i < N) excl[i] = x - v;
    if (tid == SCAN_B - 1) bsum[blockIdx.x] = x;
}

__global__ void scan2_kernel(int* __restrict__ bsum, int NB) {
    __shared__ int s[1024];
    const int tid = threadIdx.x;
    int v = (tid < NB) ? bsum[tid] : 0;
    s[tid] = v;
    __syncthreads();
    int x = v;
#pragma unroll
    for (int d = 1; d < 1024; d <<= 1) {
        int t = (tid >= d) ? s[tid - d] : 0;
        __syncthreads();
        x += t;
        s[tid] = x;
        __syncthreads();
    }
    if (tid < NB) bsum[tid] = x - v;
}

__global__ void scan3_kernel(int* __restrict__ row_start,
                             const int* __restrict__ bsum,
                             int* __restrict__ cursor, int N, int E) {
    const int i = blockIdx.x * SCAN_B + threadIdx.x;
    if (i < N) {
        int v = row_start[i] + bsum[blockIdx.x];
        row_start[i] = v;
        cursor[i] = v;
    }
    if (i == 0) row_start[N] = E;
}

__global__ void scatter_kernel(const int* __restrict__ rj,
                               const int* __restrict__ lj,
                               const float* __restrict__ w,
                               int* __restrict__ cursor,
                               float2* __restrict__ edges, int E) {
    int e = blockIdx.x * blockDim.x + threadIdx.x;
    if (e >= E) return;
    int r = __ldg(rj + e);
    int p = atomicAdd(cursor + r, 1);
    edges[p] = make_float2(__int_as_float(__ldg(lj + e)), __ldg(w + e));
}

// ======================= tf32 mma helpers ===================================
__device__ __forceinline__ uint32_t cvt_tf32(float x) {
    uint32_t u;
    asm("cvt.rna.tf32.f32 %0, %1;" : "=r"(u) : "f"(x));
    return u;
}
__device__ __forceinline__ void split_tf32(float x, uint32_t& hi, uint32_t& lo) {
    hi = cvt_tf32(x);
    lo = cvt_tf32(x - __uint_as_float(hi));
}
__device__ __forceinline__ void mma8(float* c,
                                     uint32_t a0, uint32_t a1, uint32_t a2, uint32_t a3,
                                     uint32_t b0, uint32_t b1) {
    asm volatile(
        "mma.sync.aligned.m16n8k8.row.col.f32.tf32.tf32.f32 "
        "{%0,%1,%2,%3}, {%4,%5,%6,%7}, {%8,%9}, {%0,%1,%2,%3};"
        : "+f"(c[0]), "+f"(c[1]), "+f"(c[2]), "+f"(c[3])
        : "r"(a0), "r"(a1), "r"(a2), "r"(a3), "r"(b0), "r"(b1));
}

#define AST 68  // smem stride (floats): conflict-free A frags, 16B aligned

// Stage A tile (64 rows of K=64, zero-padded past M) and W (64x64) into smem.
__device__ __forceinline__ void stage_AW(const float* __restrict__ A,
                                         const float* __restrict__ W,
                                         int block_row, int M,
                                         float* sA, float* sW, int tid) {
#pragma unroll
    for (int it = 0; it < 8; it++) {
        int i = tid + it * 128;            // 0..1023
        int r = i >> 4, c4 = (i & 15) * 4;
        int gr = block_row + r;
        float4 v = (gr < M) ? *reinterpret_cast<const float4*>(A + (size_t)gr * 64 + c4)
                            : make_float4(0.f, 0.f, 0.f, 0.f);
        *reinterpret_cast<float4*>(sA + r * AST + c4) = v;
        float4 w = *reinterpret_cast<const float4*>(W + r * 64 + c4);
        *reinterpret_cast<float4*>(sW + r * AST + c4) = w;
    }
}

// 64x64 @ 64x64 accumulate into cacc via 3xTF32 (fp32-accurate).
__device__ __forceinline__ void tile_mma(const float* sA, const float* sW,
                                         int wr, int wc, int g, int tig,
                                         float cacc[2][4][4]) {
#pragma unroll
    for (int ks = 0; ks < 8; ks++) {
        const int kb = ks * 8;
        uint32_t ahi[2][4], alo[2][4];
#pragma unroll
        for (int mt = 0; mt < 2; mt++) {
            const int base = (wr + mt * 16 + g) * AST + kb + tig;
            split_tf32(sA[base],             ahi[mt][0], alo[mt][0]);
            split_tf32(sA[base + 8 * AST],   ahi[mt][1], alo[mt][1]);
            split_tf32(sA[base + 4],         ahi[mt][2], alo[mt][2]);
            split_tf32(sA[base + 8 * AST + 4], ahi[mt][3], alo[mt][3]);
        }
#pragma unroll
        for (int nt = 0; nt < 4; nt++) {
            const int nb = wc + nt * 8;
            float w0 = sW[(kb + tig) * AST + nb + g];
            float w1 = sW[(kb + tig + 4) * AST + nb + g];
            uint32_t bh0, bl0, bh1, bl1;
            split_tf32(w0, bh0, bl0);
            split_tf32(w1, bh1, bl1);
#pragma unroll
            for (int mt = 0; mt < 2; mt++) {
                mma8(cacc[mt][nt], ahi[mt][0], ahi[mt][1], ahi[mt][2], ahi[mt][3], bh0, bh1);
                mma8(cacc[mt][nt], ahi[mt][0], ahi[mt][1], ahi[mt][2], ahi[mt][3], bl0, bl1);
                mma8(cacc[mt][nt], alo[mt][0], alo[mt][1], alo[mt][2], alo[mt][3], bh0, bh1);
            }
        }
    }
}

// ---------------- fused input GEMMs (tf32): rhs = input@Wi+bi, lhs = other@Wo
__global__ __launch_bounds__(128)
void gemm_both_tf32(const float* __restrict__ input,
                    const float* __restrict__ Wi,
                    const float* __restrict__ bi,
                    const float* __restrict__ other,
                    const float* __restrict__ Wo,
                    float* __restrict__ rhs,
                    float* __restrict__ lhs,
                    int M_in, int M_ot, int blocks_in) {
    __shared__ float sA[64 * AST];
    __shared__ float sW[64 * AST];

    const bool is_in = (int)blockIdx.x < blocks_in;
    const float* A = is_in ? input : other;
    const float* W = is_in ? Wi : Wo;
    const float* bias = is_in ? bi : nullptr;
    float* C = is_in ? rhs : lhs;
    const int M = is_in ? M_in : M_ot;
    const int block_row = (is_in ? blockIdx.x : (blockIdx.x - blocks_in)) * 64;
    const int tid = threadIdx.x;

    stage_AW(A, W, block_row, M, sA, sW, tid);
    __syncthreads();

    const int warp = tid >> 5, lane = tid & 31;
    const int g = lane >> 2, tig = lane & 3;
    const int wr = (warp & 1) * 32;
    const int wc = (warp >> 1) * 32;

    float cacc[2][4][4] = {};
    tile_mma(sA, sW, wr, wc, g, tig, cacc);

#pragma unroll
    for (int mt = 0; mt < 2; mt++) {
#pragma unroll
        for (int nt = 0; nt < 4; nt++) {
            const int col = wc + nt * 8 + tig * 2;
            float b0 = 0.f, b1 = 0.f;
            if (bias) { b0 = __ldg(bias + col); b1 = __ldg(bias + col + 1); }
            const int row0 = block_row + wr + mt * 16 + g;
            if (row0 < M)
                *reinterpret_cast<float2*>(C + (size_t)row0 * 64 + col) =
                    make_float2(cacc[mt][nt][0] + b0, cacc[mt][nt][1] + b1);
            const int row1 = row0 + 8;
            if (row1 < M)
                *reinterpret_cast<float2*>(C + (size_t)row1 * 64 + col) =
                    make_float2(cacc[mt][nt][2] + b0, cacc[mt][nt][3] + b1);
        }
    }
}

// ---------------- row accumulate (unchanged from R3) --------------------------
__device__ __forceinline__ float lrelu(float x) {
    return fmaxf(x, 0.f) + 0.01f * fminf(x, 0.f);
}

__global__ void row_kernel(const float* __restrict__ rhs,
                           const float* __restrict__ lhs,
                           const int* __restrict__ row_start,
                           const float2* __restrict__ edges,
                           const float* __restrict__ We,
                           float* __restrict__ acc, int N) {
    const int row = blockIdx.x * (blockDim.x >> 5) + (threadIdx.x >> 5);
    if (row >= N) return;
    const int lane = threadIdx.x & 31;

    const float2* rhs2 = reinterpret_cast<const float2*>(rhs);
    const float2* lhs2 = reinterpret_cast<const float2*>(lhs);
    const float2* We2  = reinterpret_cast<const float2*>(We);

    const float2 r  = __ldg(rhs2 + (size_t)row * 32 + lane);
    const float2 we = __ldg(We2 + lane);

    const int s = __ldg(row_start + row);
    const int t = __ldg(row_start + row + 1);

    float ax = 0.f, ay = 0.f, bx = 0.f, by = 0.f;
    int j = s;
#pragma unroll 2
    for (; j + 2 <= t; j += 2) {
        float2 e0 = __ldg(edges + j);
        float2 e1 = __ldg(edges + j + 1);
        int l0 = __float_as_int(e0.x);
        int l1 = __float_as_int(e1.x);
        float2 v0 = __ldg(lhs2 + (size_t)l0 * 32 + lane);
        float2 v1 = __ldg(lhs2 + (size_t)l1 * 32 + lane);
        ax += lrelu(fmaf(e0.y, we.x, r.x + v0.x));
        ay += lrelu(fmaf(e0.y, we.y, r.y + v0.y));
        bx += lrelu(fmaf(e1.y, we.x, r.x + v1.x));
        by += lrelu(fmaf(e1.y, we.y, r.y + v1.y));
    }
    if (j < t) {
        float2 e0 = __ldg(edges + j);
        int l0 = __float_as_int(e0.x);
        float2 v0 = __ldg(lhs2 + (size_t)l0 * 32 + lane);
        ax += lrelu(fmaf(e0.y, we.x, r.x + v0.x));
        ay += lrelu(fmaf(e0.y, we.y, r.y + v0.y));
    }
    reinterpret_cast<float2*>(acc)[(size_t)row * 32 + lane] =
        make_float2(ax + bx, ay + by);
}

// ---------------- precompute Wcomb = Wf@Wout[0:64,:], bfw = bf@Wout[0:64,:] ---
__global__ void precompute_kernel(const float* __restrict__ Wf,
                                  const float* __restrict__ bf,
                                  const float* __restrict__ Wout,
                                  float* __restrict__ Wcomb,
                                  float* __restrict__ bfw) {
    int tid = blockIdx.x * blockDim.x + threadIdx.x;
    if (tid < 64 * 64) {
        int k = tid >> 6, d = tid & 63;
        float s0 = 0.f, s1 = 0.f, s2 = 0.f, s3 = 0.f;
#pragma unroll
        for (int j = 0; j < 64; j += 4) {
            s0 = fmaf(__ldg(Wf + k * 64 + j + 0), __ldg(Wout + (j + 0) * 64 + d), s0);
            s1 = fmaf(__ldg(Wf + k * 64 + j + 1), __ldg(Wout + (j + 1) * 64 + d), s1);
            s2 = fmaf(__ldg(Wf + k * 64 + j + 2), __ldg(Wout + (j + 2) * 64 + d), s2);
            s3 = fmaf(__ldg(Wf + k * 64 + j + 3), __ldg(Wout + (j + 3) * 64 + d), s3);
        }
        Wcomb[tid] = (s0 + s1) + (s2 + s3);
    }
    if (tid < 64) {
        float s0 = 0.f, s1 = 0.f;
#pragma unroll
        for (int j = 0; j < 64; j += 2) {
            s0 = fmaf(__ldg(bf + j + 0), __ldg(Wout + (j + 0) * 64 + tid), s0);
            s1 = fmaf(__ldg(bf + j + 1), __ldg(Wout + (j + 1) * 64 + tid), s1);
        }
        bfw[tid] = s0 + s1;
    }
}

// ---------------- fused epilogue (tf32, K=128) + cnt term + biases ------------
__global__ __launch_bounds__(128)
void final_tf32(const float* __restrict__ accm,
                const float* __restrict__ input,
                const int* __restrict__ row_start,
                const float* __restrict__ Wcomb,
                const float* __restrict__ WoutB,
                const float* __restrict__ bfw,
                const float* __restrict__ bout,
                float* __restrict__ out, int M) {
    __shared__ float sA[64 * AST];
    __shared__ float sW[64 * AST];
    __shared__ float scnt[64];

    const int block_row = blockIdx.x * 64;
    const int tid = threadIdx.x;

    if (tid < 64) {
        int gr = block_row + tid;
        scnt[tid] = (gr < M)
            ? (float)(__ldg(row_start + gr + 1) - __ldg(row_start + gr)) : 0.f;
    }

    const int warp = tid >> 5, lane = tid & 31;
    const int g = lane >> 2, tig = lane & 3;
    const int wr = (warp & 1) * 32;
    const int wc = (warp >> 1) * 32;

    float cacc[2][4][4] = {};

#pragma unroll
    for (int p = 0; p < 2; p++) {
        const float* Ap = (p == 0) ? accm : input;
        const float* Wp = (p == 0) ? Wcomb : WoutB;
        stage_AW(Ap, Wp, block_row, M, sA, sW, tid);
        __syncthreads();
        tile_mma(sA, sW, wr, wc, g, tig, cacc);
        __syncthreads();
    }

#pragma unroll
    for (int mt = 0; mt < 2; mt++) {
#pragma unroll
        for (int nt = 0; nt < 4; nt++) {
            const int col = wc + nt * 8 + tig * 2;
            const float f0 = __ldg(bfw + col), f1 = __ldg(bfw + col + 1);
            const float o0 = __ldg(bout + col), o1 = __ldg(bout + col + 1);
            const int r0 = wr + mt * 16 + g;
            const int row0 = block_row + r0;
            if (row0 < M) {
                float c = scnt[r0];
                *reinterpret_cast<float2*>(out + (size_t)row0 * 64 + col) =
                    make_float2(cacc[mt][nt][0] + c * f0 + o0,
                                cacc[mt][nt][1] + c * f1 + o1);
            }
            const int row1 = row0 + 8;
            if (row1 < M) {
                float c = scnt[r0 + 8];
                *reinterpret_cast<float2*>(out + (size_t)row1 * 64 + col) =
                    make_float2(cacc[mt][nt][2] + c * f0 + o0,
                                cacc[mt][nt][3] + c * f1 + o1);
            }
        }
    }
}

// ---------------------------------------------------------------------------
extern "C" void kernel_launch(void* const* d_in, const int* in_sizes, int n_in,
                              void* d_out, int out_size) {
    const float* input   = (const float*)d_in[0];
    const float* other   = (const float*)d_in[1];
    const int*   rj      = (const int*)d_in[2];
    const int*   lj      = (const int*)d_in[3];
    const float* weights = (const float*)d_in[4];
    const float* Wi      = (const float*)d_in[5];
    const float* bi      = (const float*)d_in[6];
    const float* Wo      = (const float*)d_in[7];
    const float* We      = (const float*)d_in[8];
    const float* Wf      = (const float*)d_in[9];
    const float* bf      = (const float*)d_in[10];
    const float* Wout    = (const float*)d_in[11];
    const float* bout    = (const float*)d_in[12];
    float* out = (float*)d_out;

    const int N_IN = in_sizes[0] / 64;
    const int N_OT = in_sizes[1] / 64;
    const int E    = in_sizes[2];

    float *rhs, *lhs, *acc, *Wcomb, *bfw;
    float2* edges;
    int *cnt, *row_start, *cursor, *bsum;
    cudaGetSymbolAddress((void**)&rhs,       g_rhs);
    cudaGetSymbolAddress((void**)&lhs,       g_lhs);
    cudaGetSymbolAddress((void**)&acc,       g_acc);
    cudaGetSymbolAddress((void**)&cnt,       g_cnt);
    cudaGetSymbolAddress((void**)&row_start, g_row_start);
    cudaGetSymbolAddress((void**)&cursor,    g_cursor);
    cudaGetSymbolAddress((void**)&bsum,      g_bsum);
    cudaGetSymbolAddress((void**)&edges,     g_edges);
    cudaGetSymbolAddress((void**)&Wcomb,     g_Wcomb);
    cudaGetSymbolAddress((void**)&bfw,       g_bfw);

    const int NB = (N_IN + SCAN_B - 1) / SCAN_B;

    // 1. counting sort of edges by rj
    zero_cnt_kernel<<<(N_IN + 255) / 256, 256>>>(cnt, N_IN);
    hist_kernel<<<(E + 255) / 256, 256>>>(rj, cnt, E);
    scan1_kernel<<<NB, SCAN_B>>>(cnt, row_start, bsum, N_IN);
    scan2_kernel<<<1, 1024>>>(bsum, NB);
    scan3_kernel<<<NB, SCAN_B>>>(row_start, bsum, cursor, N_IN, E);
    scatter_kernel<<<(E + 255) / 256, 256>>>(rj, lj, weights, cursor, edges, E);

    // 2. fused input-side GEMMs (tensor cores, 3xTF32)
    {
        int blocks_in = (N_IN + 63) / 64;
        int blocks_ot = (N_OT + 63) / 64;
        gemm_both_tf32<<<blocks_in + blocks_ot, 128>>>(
            input, Wi, bi, other, Wo, rhs, lhs, N_IN, N_OT, blocks_in);
    }

    // 3. per-row edge accumulation
    row_kernel<<<(N_IN + 7) / 8, 256>>>(rhs, lhs, row_start, edges, We, acc, N_IN);

    // 4. folded epilogue weights
    precompute_kernel<<<16, 256>>>(Wf, bf, Wout, Wcomb, bfw);

    // 5. fused epilogue GEMM (tensor cores, K=128) + cnt*bfw + bout
    final_tf32<<<(N_IN + 63) / 64, 128>>>(acc, input, row_start, Wcomb,
                                          Wout + 64 * 64, bfw, bout, out, N_IN);
}